// round 15
// baseline (speedup 1.0000x reference)
#include <cuda_runtime.h>
#include <cuda_fp16.h>
#include <cstdint>
#include <cstddef>
#include <math.h>

#define SQ  512
#define HID 2048
#define NZ  64
#define MR  8192
#define K3A 1536
#define K2A 1024
#define K3P 6144
#define K2P 4096

static const float SCALE_F = 0.04419417382415922f;

// ------------------------- scratch -------------------------
__device__ __align__(1024) __half g_x3  [(size_t)MR*K3P];   // [h|h|l]; first 4096 cols = [h|h]
__device__ __align__(1024) __half g_w3  [(size_t)3*HID*K3P];
__device__ __align__(1024) __half g_w2  [(size_t)2*HID*K2P];
__device__ __align__(1024) float  g_ypv [(size_t)MR*HID];
__device__ __align__(1024) float  g_ypcv[(size_t)MR*HID];
__device__ __align__(1024) __half g_q3  [(size_t)NZ*SQ*K3A];
__device__ __align__(1024) __half g_k3  [(size_t)NZ*SQ*K3A];
__device__ __align__(1024) __half g_ck3 [(size_t)NZ*SQ*K3A];
__device__ __align__(1024) __half g_vT2 [(size_t)NZ*SQ*K2A];
__device__ __align__(1024) __half g_cvT2[(size_t)NZ*SQ*K2A];
__device__ __align__(1024) __half g_s13 [(size_t)NZ*SQ*K3A];
__device__ __align__(1024) float  g_s2  [(size_t)NZ*SQ*SQ];
__device__ __align__(1024) __half g_p2  [(size_t)NZ*SQ*K2A];
__device__ __align__(1024) __half g_c2  [(size_t)NZ*SQ*K2A];

// ------------------------- helpers -------------------------
#define CP16(dst, src) asm volatile("cp.async.cg.shared.global [%0], [%1], 16;" \
    :: "r"(dst), "l"(src))
#define CP_COMMIT() asm volatile("cp.async.commit_group;")
#define CP_WAIT(n)  asm volatile("cp.async.wait_group %0;" :: "n"(n))

__device__ __forceinline__ void ldsm4(uint32_t* d, uint32_t addr) {
    asm volatile("ldmatrix.sync.aligned.m8n8.x4.shared.b16 {%0,%1,%2,%3}, [%4];"
        : "=r"(d[0]), "=r"(d[1]), "=r"(d[2]), "=r"(d[3]) : "r"(addr));
}
__device__ __forceinline__ void mma16816(float* c, const uint32_t* a, uint32_t b0, uint32_t b1) {
    asm volatile("mma.sync.aligned.m16n8k16.row.col.f32.f16.f16.f32 "
        "{%0,%1,%2,%3}, {%4,%5,%6,%7}, {%8,%9}, {%0,%1,%2,%3};"
        : "+f"(c[0]), "+f"(c[1]), "+f"(c[2]), "+f"(c[3])
        : "r"(a[0]), "r"(a[1]), "r"(a[2]), "r"(a[3]), "r"(b0), "r"(b1));
}
__device__ __forceinline__ void splitH2(float x, float y, uint32_t& h2, uint32_t& l2) {
    __half2 h, l;
    h.x = __float2half_rn(x); l.x = __float2half_rn(x - __half2float(h.x));
    h.y = __float2half_rn(y); l.y = __float2half_rn(y - __half2float(h.y));
    h2 = *reinterpret_cast<uint32_t*>(&h);
    l2 = *reinterpret_cast<uint32_t*>(&l);
}

struct Ptrs { const float* bias[3]; void* out5[3]; };
struct WPtr { const float* w[5]; };

#define STGB 10240u
#define NSTG 5
#define SMEM_REQ (2u * NSTG * STGB)

// ------------------------- GEMM (mma.sync f16->f32, NT) ---------------------
// EPI 0: fp32 out; EPI 1: s1 A-cat3; EPI 2: proj3 head-remap cat3;
// EPI 3: proj2 fp32+bias; EPI 4: ctx A-cat2
template <int EPI>
__global__ __launch_bounds__(256, 2) void gemm_mma(
    const __half* __restrict__ A, long long sAz, int lda,
    const __half* __restrict__ B, long long sBz, int ldb,
    void* outp, float alpha, int K,
    long long sZ, long long sCb, long long sCh, int ldc, Ptrs pp)
{
    extern __shared__ char smraw[];
    const uint32_t baseA = (uint32_t)__cvta_generic_to_shared(smraw);
    const uint32_t baseB = baseA + NSTG * STGB;

    const int tid = threadIdx.x;
    const int lane = tid & 31, wid = tid >> 5;
    const int wm = wid >> 2, wn = wid & 3;
    const int m0 = blockIdx.y * 128, n0 = blockIdx.x * 128, z = blockIdx.z;

    const __half* Az = A + (size_t)z * sAz;
    const __half* Bz = B + (size_t)z * sBz;

    const int lr = tid >> 2, lq = tid & 3;
    const __half* gA0 = Az + (size_t)(m0 + lr) * lda + lq * 8;
    const __half* gA1 = Az + (size_t)(m0 + lr + 64) * lda + lq * 8;
    const __half* gB0 = Bz + (size_t)(n0 + lr) * ldb + lq * 8;
    const __half* gB1 = Bz + (size_t)(n0 + lr + 64) * ldb + lq * 8;

    const uint32_t dA0 = baseA + lr * 80 + lq * 16;
    const uint32_t dA1 = baseA + (lr + 64) * 80 + lq * 16;
    const uint32_t dB0 = baseB + lr * 80 + lq * 16;
    const uint32_t dB1 = baseB + (lr + 64) * 80 + lq * 16;

    const int lrow = (lane & 7) + ((lane >> 3) & 1) * 8;
    const int lchunk = lane >> 4;
    const uint32_t aAddr = (wm * 64 + lrow) * 80 + lchunk * 16;
    const uint32_t bAddr = (wn * 32 + lrow) * 80 + lchunk * 16;

    float acc[4][4][4];
#pragma unroll
    for (int i = 0; i < 4; i++)
#pragma unroll
        for (int j = 0; j < 4; j++) { acc[i][j][0]=0.f; acc[i][j][1]=0.f; acc[i][j][2]=0.f; acc[i][j][3]=0.f; }

#define LOADTILE(kt, st) do { \
    const size_t ko = (size_t)(kt) * 32; \
    const uint32_t so = (uint32_t)(st) * STGB; \
    CP16(dA0 + so, gA0 + ko); CP16(dA1 + so, gA1 + ko); \
    CP16(dB0 + so, gB0 + ko); CP16(dB1 + so, gB1 + ko); \
} while (0)

#define COMPUTE_CHUNK(st) do { \
    const uint32_t so = (uint32_t)(st) * STGB; \
    _Pragma("unroll") \
    for (int k16 = 0; k16 < 2; ++k16) { \
        const uint32_t kb = so + k16 * 32; \
        uint32_t a[4][4], bq[2][4]; \
        _Pragma("unroll") \
        for (int mi = 0; mi < 4; ++mi) ldsm4(a[mi], baseA + kb + aAddr + mi * (16*80)); \
        _Pragma("unroll") \
        for (int j = 0; j < 2; ++j) ldsm4(bq[j], baseB + kb + bAddr + j * (16*80)); \
        _Pragma("unroll") \
        for (int mi = 0; mi < 4; ++mi) \
            _Pragma("unroll") \
            for (int ni = 0; ni < 4; ++ni) \
                mma16816(acc[mi][ni], a[mi], bq[ni >> 1][ni & 1], bq[ni >> 1][2 + (ni & 1)]); \
    } \
} while (0)

    const int KT = K / 32;
    LOADTILE(0, 0); CP_COMMIT();
    LOADTILE(1, 1); CP_COMMIT();
    LOADTILE(2, 2); CP_COMMIT();

    int cs = 0, ls = 3;
    for (int kt = 0; kt < KT; kt += 2) {
        CP_WAIT(1);
        __syncthreads();
        const int ls2 = (ls + 1 == NSTG) ? 0 : ls + 1;
        if (kt + 3 < KT) { LOADTILE(kt + 3, ls); CP_COMMIT(); } else CP_COMMIT();
        if (kt + 4 < KT) { LOADTILE(kt + 4, ls2); CP_COMMIT(); } else CP_COMMIT();
        const int cs2 = (cs + 1 == NSTG) ? 0 : cs + 1;
        COMPUTE_CHUNK(cs);
        COMPUTE_CHUNK(cs2);
        cs = (cs2 + 1 == NSTG) ? 0 : cs2 + 1;
        ls = (ls2 + 1 == NSTG) ? 0 : ls2 + 1;
    }
#undef LOADTILE
#undef COMPUTE_CHUNK

    float* obase = nullptr;
    __half* cbase = nullptr;
    if (EPI == 0) obase = (float*)outp + (size_t)z * sZ + (size_t)(z >> 2) * sCb + (size_t)(z & 3) * sCh;
    if (EPI == 1) cbase = (__half*)outp + (size_t)z * SQ * K3A;
    if (EPI == 4) cbase = (__half*)outp + (size_t)z * SQ * K2A;
    const bool modeB = (z != 0);

#pragma unroll
    for (int mi = 0; mi < 4; ++mi)
#pragma unroll
        for (int ni = 0; ni < 4; ++ni) {
            const int r0 = m0 + wm * 64 + mi * 16 + (lane >> 2);
            const int c  = n0 + wn * 32 + ni * 8 + (lane & 3) * 2;
#pragma unroll
            for (int hh = 0; hh < 2; ++hh) {
                const int r = r0 + hh * 8;
                float v0 = acc[mi][ni][hh * 2], v1 = acc[mi][ni][hh * 2 + 1];
                if (EPI == 0) {
                    float2 f; f.x = v0 * alpha; f.y = v1 * alpha;
                    *(float2*)(obase + (size_t)r * ldc + c) = f;
                } else if (EPI == 1) {
                    uint32_t h2, l2; splitH2(v0, v1, h2, l2);
                    __half* o = cbase + (size_t)r * K3A + c;
                    *(uint32_t*)o = h2; *(uint32_t*)(o + 512) = h2; *(uint32_t*)(o + 1024) = l2;
                } else if (EPI == 4) {
                    uint32_t h2, l2; splitH2(v0, v1, h2, l2);
                    __half* o = cbase + (size_t)r * K2A + c;
                    *(uint32_t*)o = h2; *(uint32_t*)(o + 512) = h2;
                } else if (EPI == 3) {
                    v0 += pp.bias[z][c]; v1 += pp.bias[z][c + 1];
                    float2 f; f.x = v0; f.y = v1;
                    *(float2*)((float*)pp.out5[z] + (size_t)r * HID + c) = f;
                } else {   // EPI == 2
                    v0 += pp.bias[z][c]; v1 += pp.bias[z][c + 1];
                    uint32_t h2, l2; splitH2(v0, v1, h2, l2);
                    const int head = ((r >> 9) << 2) + (c >> 9);
                    __half* o = (__half*)pp.out5[z]
                        + ((size_t)(head * 512 + (r & 511))) * K3A + (c & 511);
                    *(uint32_t*)o = h2;
                    *(uint32_t*)(o + 512)  = modeB ? l2 : h2;
                    *(uint32_t*)(o + 1024) = modeB ? h2 : l2;
                }
            }
        }
}

// ------------------------- conversions -------------------------
// One launch for X + all 5 weights. grid (8, 2048, 9):
//   z 0..3  -> X rows z*2048 + y  (A-cat3 [h|h|l])
//   z 4..6  -> w3[z-4] (q,k,ck) B-cat3 [h|l|h]
//   z 7..8  -> w2[z-7] (v,cv)   B-cat2 [h|l]
__global__ void conv_all(const float* __restrict__ X, WPtr wp,
                         __half* __restrict__ x3,
                         __half* __restrict__ w3, __half* __restrict__ w2)
{
    const int z = blockIdx.z;
    const int y = blockIdx.y;
    const int k = (blockIdx.x * blockDim.x + threadIdx.x) * 2;
    if (z < 4) {
        const int r = z * 2048 + y;
        float2 x = *(const float2*)(X + (size_t)r * HID + k);
        uint32_t h2, l2; splitH2(x.x, x.y, h2, l2);
        __half* o3 = x3 + (size_t)r * K3P + k;
        *(uint32_t*)o3             = h2;
        *(uint32_t*)(o3 + HID)     = h2;
        *(uint32_t*)(o3 + 2 * HID) = l2;
    } else if (z < 7) {
        const int w = z - 4;
        float2 x = *(const float2*)(wp.w[w] + (size_t)y * HID + k);
        uint32_t h2, l2; splitH2(x.x, x.y, h2, l2);
        __half* o = w3 + ((size_t)w * HID + y) * K3P + k;
        *(uint32_t*)o             = h2;
        *(uint32_t*)(o + HID)     = l2;
        *(uint32_t*)(o + 2 * HID) = h2;
    } else {
        const int w = z - 7;
        float2 x = *(const float2*)(wp.w[3 + w] + (size_t)y * HID + k);
        uint32_t h2, l2; splitH2(x.x, x.y, h2, l2);
        __half* o = w2 + ((size_t)w * HID + y) * K2P + k;
        *(uint32_t*)o         = h2;
        *(uint32_t*)(o + HID) = l2;
    }
}

__global__ void convT2(const float* __restrict__ in, __half* __restrict__ out)
{
    __shared__ float t[32][33];
    const int r0 = blockIdx.y * 32, c0 = blockIdx.x * 32;
    const int tx = threadIdx.x, ty = threadIdx.y;
#pragma unroll
    for (int i = ty; i < 32; i += 8)
        t[i][tx] = in[(size_t)(r0 + i) * HID + c0 + tx];
    __syncthreads();
#pragma unroll
    for (int i = ty; i < 32; i += 8) {
        float x = t[tx][i];
        const int s = (r0 + tx) & 511;
        const int head = ((r0 >> 9) << 2) + ((c0 + i) >> 9);
        const int dd = (c0 + i) & 511;
        __half h = __float2half_rn(x);
        __half l = __float2half_rn(x - __half2float(h));
        __half* o = out + ((size_t)(head * 512 + dd)) * K2A + s;
        o[0] = h; o[512] = l;
    }
}

__global__ __launch_bounds__(128) void softmax_h(const float* __restrict__ S,
                                                 __half* __restrict__ P)
{
    const size_t row = blockIdx.x;
    const int t = threadIdx.x;
    float4 v = ((const float4*)(S + row * SQ))[t];
    float m = fmaxf(fmaxf(v.x, v.y), fmaxf(v.z, v.w));
#pragma unroll
    for (int o = 16; o; o >>= 1) m = fmaxf(m, __shfl_xor_sync(0xffffffffu, m, o));
    __shared__ float rm[4];
    if ((t & 31) == 0) rm[t >> 5] = m;
    __syncthreads();
    m = fmaxf(fmaxf(rm[0], rm[1]), fmaxf(rm[2], rm[3]));
    v.x = expf(v.x - m); v.y = expf(v.y - m); v.z = expf(v.z - m); v.w = expf(v.w - m);
    float s = v.x + v.y + v.z + v.w;
#pragma unroll
    for (int o = 16; o; o >>= 1) s += __shfl_xor_sync(0xffffffffu, s, o);
    __shared__ float rs[4];
    if ((t & 31) == 0) rs[t >> 5] = s;
    __syncthreads();
    s = rs[0] + rs[1] + rs[2] + rs[3];
    const float inv = 1.0f / s;
    __half2 h0, h1;
    h0.x = __float2half_rn(v.x * inv); h0.y = __float2half_rn(v.y * inv);
    h1.x = __float2half_rn(v.z * inv); h1.y = __float2half_rn(v.w * inv);
    __half* o = P + row * K2A + t * 4;
    *(__half2*)o         = h0; *(__half2*)(o + 2)   = h1;
    *(__half2*)(o + 512) = h0; *(__half2*)(o + 514) = h1;
}

// ------------------------- host -------------------------
extern "C" void kernel_launch(void* const* d_in, const int* in_sizes, int n_in,
                              void* d_out, int out_size)
{
    const float* X = (const float*)d_in[0];
    WPtr wp = {{(const float*)d_in[1], (const float*)d_in[3], (const float*)d_in[7],
                (const float*)d_in[5], (const float*)d_in[9]}};
    const float* bq  = (const float*)d_in[2];
    const float* bk  = (const float*)d_in[4];
    const float* bv  = (const float*)d_in[6];
    const float* bck = (const float*)d_in[8];
    const float* bcv = (const float*)d_in[10];

    void *x3, *w3, *w2, *ypv, *ypcv, *q3, *k3, *ck3, *vT2, *cvT2, *s13, *s2, *p2, *c2;
    cudaGetSymbolAddress(&x3, g_x3);
    cudaGetSymbolAddress(&w3, g_w3);     cudaGetSymbolAddress(&w2, g_w2);
    cudaGetSymbolAddress(&ypv, g_ypv);   cudaGetSymbolAddress(&ypcv, g_ypcv);
    cudaGetSymbolAddress(&q3, g_q3);     cudaGetSymbolAddress(&k3, g_k3);
    cudaGetSymbolAddress(&ck3, g_ck3);   cudaGetSymbolAddress(&vT2, g_vT2);
    cudaGetSymbolAddress(&cvT2, g_cvT2); cudaGetSymbolAddress(&s13, g_s13);
    cudaGetSymbolAddress(&s2, g_s2);     cudaGetSymbolAddress(&p2, g_p2);
    cudaGetSymbolAddress(&c2, g_c2);

    Ptrs pp3;
    pp3.bias[0] = bq;  pp3.out5[0] = q3;
    pp3.bias[1] = bk;  pp3.out5[1] = k3;
    pp3.bias[2] = bck; pp3.out5[2] = ck3;
    Ptrs pp2;
    pp2.bias[0] = bv;  pp2.out5[0] = ypv;
    pp2.bias[1] = bcv; pp2.out5[1] = ypcv;
    pp2.bias[2] = bv;  pp2.out5[2] = ypv;
    Ptrs pz = pp3;

    static bool init_done = false;
    static cudaStream_t sB;
    static cudaEvent_t evRoot, evB, evProj, evEnd;
    if (!init_done) {
        cudaFuncSetAttribute(gemm_mma<0>, cudaFuncAttributeMaxDynamicSharedMemorySize, SMEM_REQ);
        cudaFuncSetAttribute(gemm_mma<1>, cudaFuncAttributeMaxDynamicSharedMemorySize, SMEM_REQ);
        cudaFuncSetAttribute(gemm_mma<2>, cudaFuncAttributeMaxDynamicSharedMemorySize, SMEM_REQ);
        cudaFuncSetAttribute(gemm_mma<3>, cudaFuncAttributeMaxDynamicSharedMemorySize, SMEM_REQ);
        cudaFuncSetAttribute(gemm_mma<4>, cudaFuncAttributeMaxDynamicSharedMemorySize, SMEM_REQ);
        cudaStreamCreateWithFlags(&sB, cudaStreamNonBlocking);
        cudaEventCreateWithFlags(&evRoot, cudaEventDisableTiming);
        cudaEventCreateWithFlags(&evB, cudaEventDisableTiming);
        cudaEventCreateWithFlags(&evProj, cudaEventDisableTiming);
        cudaEventCreateWithFlags(&evEnd, cudaEventDisableTiming);
        init_done = true;
    }

    const long long s3 = (long long)SQ * K3A;
    const long long s2a = (long long)SQ * K2A;
    const size_t zo3  = (size_t)32 * SQ * K3A;   // head-group offset (32 heads)
    const size_t zo2  = (size_t)32 * SQ * K2A;
    const size_t zoS  = (size_t)32 * SQ * SQ;
    const size_t zoO  = (size_t)8 * SQ * HID;    // 8 batches
    dim3 gh(SQ / 128, SQ / 128, 32);             // per-group grid (512 CTAs)

    // launch 0: all conversions in one kernel
    conv_all<<<dim3(8, 2048, 9), 128>>>(X, wp, (__half*)x3, (__half*)w3, (__half*)w2);
    cudaEventRecord(evRoot, 0);

    // branch B: proj2 (v,cv) + transposes
    cudaStreamWaitEvent(sB, evRoot, 0);
    gemm_mma<3><<<dim3(HID / 128, MR / 128, 2), 256, SMEM_REQ, sB>>>(
        (const __half*)x3, 0LL, K3P, (const __half*)w2, (long long)HID * K2P, K2P,
        nullptr, 1.0f, K2P, 0, 0, 0, 0, pp2);
    convT2<<<dim3(HID / 32, MR / 32), dim3(32, 8), 0, sB>>>((const float*)ypv, (__half*)vT2);
    convT2<<<dim3(HID / 32, MR / 32), dim3(32, 8), 0, sB>>>((const float*)ypcv, (__half*)cvT2);
    cudaEventRecord(evB, sB);

    // proj3 (default stream)
    gemm_mma<2><<<dim3(HID / 128, MR / 128, 3), 256, SMEM_REQ>>>(
        (const __half*)x3, 0LL, K3P, (const __half*)w3, (long long)HID * K3P, K3P,
        nullptr, 1.0f, K3P, 0, 0, 0, 0, pp3);
    cudaEventRecord(evProj, 0);

    // ----- group 1 (heads 32..63 = batches 8..15) on sB -----
    cudaStreamWaitEvent(sB, evProj, 0);
    gemm_mma<1><<<gh, 256, SMEM_REQ, sB>>>(
        (const __half*)q3 + zo3, s3, K3A, (const __half*)k3 + zo3, s3, K3A,
        (__half*)s13 + zo3, 1.0f, K3A, 0, 0, 0, 0, pz);
    gemm_mma<0><<<gh, 256, SMEM_REQ, sB>>>(
        (const __half*)s13 + zo3, s3, K3A, (const __half*)ck3 + zo3, s3, K3A,
        (float*)s2 + zoS, SCALE_F, K3A, (long long)SQ * SQ, 0, 0, SQ, pz);
    softmax_h<<<32 * SQ, 128, 0, sB>>>((const float*)s2 + zoS, (__half*)p2 + zo2);
    gemm_mma<4><<<gh, 256, SMEM_REQ, sB>>>(
        (const __half*)p2 + zo2, s2a, K2A, (const __half*)vT2 + zo2, s2a, K2A,
        (__half*)c2 + zo2, 1.0f, K2A, 0, 0, 0, 0, pz);
    gemm_mma<0><<<gh, 256, SMEM_REQ, sB>>>(
        (const __half*)c2 + zo2, s2a, K2A, (const __half*)cvT2 + zo2, s2a, K2A,
        (float*)d_out + zoO, 1.0f, K2A, 0, (long long)SQ * HID, 512, HID, pz);
    cudaEventRecord(evEnd, sB);

    // ----- group 0 (heads 0..31 = batches 0..7) on default stream -----
    gemm_mma<1><<<gh, 256, SMEM_REQ>>>(
        (const __half*)q3, s3, K3A, (const __half*)k3, s3, K3A,
        s13, 1.0f, K3A, 0, 0, 0, 0, pz);
    gemm_mma<0><<<gh, 256, SMEM_REQ>>>(
        (const __half*)s13, s3, K3A, (const __half*)ck3, s3, K3A,
        s2, SCALE_F, K3A, (long long)SQ * SQ, 0, 0, SQ, pz);
    softmax_h<<<32 * SQ, 128>>>((const float*)s2, (__half*)p2);
    cudaStreamWaitEvent(0, evB, 0);
    gemm_mma<4><<<gh, 256, SMEM_REQ>>>(
        (const __half*)p2, s2a, K2A, (const __half*)vT2, s2a, K2A,
        c2, 1.0f, K2A, 0, 0, 0, 0, pz);
    gemm_mma<0><<<gh, 256, SMEM_REQ>>>(
        (const __half*)c2, s2a, K2A, (const __half*)cvT2, s2a, K2A,
        d_out, 1.0f, K2A, 0, (long long)SQ * HID, 512, HID, pz);

    // join sB back into the harness's stream
    cudaStreamWaitEvent(0, evEnd, 0);
}

// round 16
// speedup vs baseline: 1.0114x; 1.0114x over previous
#include <cuda_runtime.h>
#include <cuda_fp16.h>
#include <cstdint>
#include <cstddef>
#include <math.h>

#define SQ  512
#define HID 2048
#define NZ  64
#define MR  8192
#define K3A 1536
#define K2A 1024
#define K3P 6144
#define K2P 4096

static const float SCALE_F = 0.04419417382415922f;

// ------------------------- scratch -------------------------
__device__ __align__(1024) __half g_x3  [(size_t)MR*K3P];   // [h|h|l]
__device__ __align__(1024) __half g_w3  [(size_t)3*HID*K3P];
__device__ __align__(1024) __half g_w2  [(size_t)2*HID*K2P];
__device__ __align__(1024) float  g_ypv [(size_t)MR*HID];
__device__ __align__(1024) float  g_ypcv[(size_t)MR*HID];
__device__ __align__(1024) __half g_q3  [(size_t)NZ*SQ*K3A];
__device__ __align__(1024) __half g_k3  [(size_t)NZ*SQ*K3A];
__device__ __align__(1024) __half g_ck3 [(size_t)NZ*SQ*K3A];
__device__ __align__(1024) __half g_vT2 [(size_t)NZ*SQ*K2A];
__device__ __align__(1024) __half g_cvT2[(size_t)NZ*SQ*K2A];
__device__ __align__(1024) __half g_s1hl[(size_t)NZ*SQ*K2A];  // s1 [h|l]
__device__ __align__(1024) float  g_s2  [(size_t)NZ*SQ*SQ];
__device__ __align__(1024) __half g_ph  [(size_t)NZ*SQ*SQ];   // P single-h
__device__ __align__(1024) __half g_ch  [(size_t)NZ*SQ*SQ];   // ctx single-h

// ------------------------- helpers -------------------------
#define CP16(dst, src) asm volatile("cp.async.cg.shared.global [%0], [%1], 16;" \
    :: "r"(dst), "l"(src))
#define CP_COMMIT() asm volatile("cp.async.commit_group;")
#define CP_WAIT(n)  asm volatile("cp.async.wait_group %0;" :: "n"(n))

__device__ __forceinline__ void ldsm4(uint32_t* d, uint32_t addr) {
    asm volatile("ldmatrix.sync.aligned.m8n8.x4.shared.b16 {%0,%1,%2,%3}, [%4];"
        : "=r"(d[0]), "=r"(d[1]), "=r"(d[2]), "=r"(d[3]) : "r"(addr));
}
__device__ __forceinline__ void mma16816(float* c, const uint32_t* a, uint32_t b0, uint32_t b1) {
    asm volatile("mma.sync.aligned.m16n8k16.row.col.f32.f16.f16.f32 "
        "{%0,%1,%2,%3}, {%4,%5,%6,%7}, {%8,%9}, {%0,%1,%2,%3};"
        : "+f"(c[0]), "+f"(c[1]), "+f"(c[2]), "+f"(c[3])
        : "r"(a[0]), "r"(a[1]), "r"(a[2]), "r"(a[3]), "r"(b0), "r"(b1));
}
__device__ __forceinline__ void splitH2(float x, float y, uint32_t& h2, uint32_t& l2) {
    __half2 h, l;
    h.x = __float2half_rn(x); l.x = __float2half_rn(x - __half2float(h.x));
    h.y = __float2half_rn(y); l.y = __float2half_rn(y - __half2float(h.y));
    h2 = *reinterpret_cast<uint32_t*>(&h);
    l2 = *reinterpret_cast<uint32_t*>(&l);
}

struct Ptrs { const float* bias[3]; void* out5[3]; };
struct WPtr { const float* w[5]; };

#define STGB 10240u
#define NSTG 5
#define SMEM_REQ (2u * NSTG * STGB)

// ------------------------- GEMM (mma.sync f16->f32, NT) ---------------------
// EPI 0: fp32 out; EPI 1: s1 [h|l] (K2A-wide); EPI 2: proj3 head-remap cat3;
// EPI 3: proj2 fp32+bias; EPI 4: single-h out (512-wide)
// AMAP: 0 = A chunk kt; 2 = kt&15 (A 512-wide, h reused); 3 = kt<16?kt:kt-16
//       (A 1024-wide [h|l] against B [h|l|h])
template <int EPI, int AMAP>
__global__ __launch_bounds__(256, 2) void gemm_mma(
    const __half* __restrict__ A, long long sAz, int lda,
    const __half* __restrict__ B, long long sBz, int ldb,
    void* outp, float alpha, int K,
    long long sZ, long long sCb, long long sCh, int ldc, Ptrs pp)
{
    extern __shared__ char smraw[];
    const uint32_t baseA = (uint32_t)__cvta_generic_to_shared(smraw);
    const uint32_t baseB = baseA + NSTG * STGB;

    const int tid = threadIdx.x;
    const int lane = tid & 31, wid = tid >> 5;
    const int wm = wid >> 2, wn = wid & 3;
    const int m0 = blockIdx.y * 128, n0 = blockIdx.x * 128, z = blockIdx.z;

    const __half* Az = A + (size_t)z * sAz;
    const __half* Bz = B + (size_t)z * sBz;

    const int lr = tid >> 2, lq = tid & 3;
    const __half* gA0 = Az + (size_t)(m0 + lr) * lda + lq * 8;
    const __half* gA1 = Az + (size_t)(m0 + lr + 64) * lda + lq * 8;
    const __half* gB0 = Bz + (size_t)(n0 + lr) * ldb + lq * 8;
    const __half* gB1 = Bz + (size_t)(n0 + lr + 64) * ldb + lq * 8;

    const uint32_t dA0 = baseA + lr * 80 + lq * 16;
    const uint32_t dA1 = baseA + (lr + 64) * 80 + lq * 16;
    const uint32_t dB0 = baseB + lr * 80 + lq * 16;
    const uint32_t dB1 = baseB + (lr + 64) * 80 + lq * 16;

    const int lrow = (lane & 7) + ((lane >> 3) & 1) * 8;
    const int lchunk = lane >> 4;
    const uint32_t aAddr = (wm * 64 + lrow) * 80 + lchunk * 16;
    const uint32_t bAddr = (wn * 32 + lrow) * 80 + lchunk * 16;

    float acc[4][4][4];
#pragma unroll
    for (int i = 0; i < 4; i++)
#pragma unroll
        for (int j = 0; j < 4; j++) { acc[i][j][0]=0.f; acc[i][j][1]=0.f; acc[i][j][2]=0.f; acc[i][j][3]=0.f; }

#define AOFF(kt) ((size_t)((AMAP == 0) ? (kt) : (AMAP == 2) ? ((kt) & 15) : (((kt) < 16) ? (kt) : (kt) - 16)) * 32)

#define LOADTILE(kt, st) do { \
    const size_t ka = AOFF(kt); \
    const size_t kb_ = (size_t)(kt) * 32; \
    const uint32_t so = (uint32_t)(st) * STGB; \
    CP16(dA0 + so, gA0 + ka); CP16(dA1 + so, gA1 + ka); \
    CP16(dB0 + so, gB0 + kb_); CP16(dB1 + so, gB1 + kb_); \
} while (0)

#define COMPUTE_CHUNK(st) do { \
    const uint32_t so = (uint32_t)(st) * STGB; \
    _Pragma("unroll") \
    for (int k16 = 0; k16 < 2; ++k16) { \
        const uint32_t kb = so + k16 * 32; \
        uint32_t a[4][4], bq[2][4]; \
        _Pragma("unroll") \
        for (int mi = 0; mi < 4; ++mi) ldsm4(a[mi], baseA + kb + aAddr + mi * (16*80)); \
        _Pragma("unroll") \
        for (int j = 0; j < 2; ++j) ldsm4(bq[j], baseB + kb + bAddr + j * (16*80)); \
        _Pragma("unroll") \
        for (int mi = 0; mi < 4; ++mi) \
            _Pragma("unroll") \
            for (int ni = 0; ni < 4; ++ni) \
                mma16816(acc[mi][ni], a[mi], bq[ni >> 1][ni & 1], bq[ni >> 1][2 + (ni & 1)]); \
    } \
} while (0)

    const int KT = K / 32;
    LOADTILE(0, 0); CP_COMMIT();
    LOADTILE(1, 1); CP_COMMIT();
    LOADTILE(2, 2); CP_COMMIT();

    int cs = 0, ls = 3;
    for (int kt = 0; kt < KT; kt += 2) {
        CP_WAIT(1);
        __syncthreads();
        const int ls2 = (ls + 1 == NSTG) ? 0 : ls + 1;
        if (kt + 3 < KT) { LOADTILE(kt + 3, ls); CP_COMMIT(); } else CP_COMMIT();
        if (kt + 4 < KT) { LOADTILE(kt + 4, ls2); CP_COMMIT(); } else CP_COMMIT();
        const int cs2 = (cs + 1 == NSTG) ? 0 : cs + 1;
        COMPUTE_CHUNK(cs);
        COMPUTE_CHUNK(cs2);
        cs = (cs2 + 1 == NSTG) ? 0 : cs2 + 1;
        ls = (ls2 + 1 == NSTG) ? 0 : ls2 + 1;
    }
#undef LOADTILE
#undef COMPUTE_CHUNK
#undef AOFF

    float* obase = nullptr;
    __half* cbase = nullptr;
    if (EPI == 0) obase = (float*)outp + (size_t)z * sZ + (size_t)(z >> 2) * sCb + (size_t)(z & 3) * sCh;
    if (EPI == 1) cbase = (__half*)outp + (size_t)z * SQ * K2A;
    if (EPI == 4) cbase = (__half*)outp + (size_t)z * SQ * 512;
    const bool modeB = (z != 0);

#pragma unroll
    for (int mi = 0; mi < 4; ++mi)
#pragma unroll
        for (int ni = 0; ni < 4; ++ni) {
            const int r0 = m0 + wm * 64 + mi * 16 + (lane >> 2);
            const int c  = n0 + wn * 32 + ni * 8 + (lane & 3) * 2;
#pragma unroll
            for (int hh = 0; hh < 2; ++hh) {
                const int r = r0 + hh * 8;
                float v0 = acc[mi][ni][hh * 2], v1 = acc[mi][ni][hh * 2 + 1];
                if (EPI == 0) {
                    float2 f; f.x = v0 * alpha; f.y = v1 * alpha;
                    *(float2*)(obase + (size_t)r * ldc + c) = f;
                } else if (EPI == 1) {
                    uint32_t h2, l2; splitH2(v0, v1, h2, l2);
                    __half* o = cbase + (size_t)r * K2A + c;
                    *(uint32_t*)o = h2; *(uint32_t*)(o + 512) = l2;
                } else if (EPI == 4) {
                    uint32_t h2, l2; splitH2(v0, v1, h2, l2);
                    __half* o = cbase + (size_t)r * 512 + c;
                    *(uint32_t*)o = h2;
                } else if (EPI == 3) {
                    v0 += pp.bias[z][c]; v1 += pp.bias[z][c + 1];
                    float2 f; f.x = v0; f.y = v1;
                    *(float2*)((float*)pp.out5[z] + (size_t)r * HID + c) = f;
                } else {   // EPI == 2
                    v0 += pp.bias[z][c]; v1 += pp.bias[z][c + 1];
                    uint32_t h2, l2; splitH2(v0, v1, h2, l2);
                    const int head = ((r >> 9) << 2) + (c >> 9);
                    __half* o = (__half*)pp.out5[z]
                        + ((size_t)(head * 512 + (r & 511))) * K3A + (c & 511);
                    *(uint32_t*)o = h2;
                    *(uint32_t*)(o + 512)  = modeB ? l2 : h2;
                    *(uint32_t*)(o + 1024) = modeB ? h2 : l2;
                }
            }
        }
}

// ------------------------- conversions -------------------------
__global__ void conv_x(const float* __restrict__ in, __half* __restrict__ x3)
{
    const int r = blockIdx.y;
    const int k = (blockIdx.x * blockDim.x + threadIdx.x) * 2;
    float2 x = *(const float2*)(in + (size_t)r * HID + k);
    uint32_t h2, l2; splitH2(x.x, x.y, h2, l2);
    __half* o3 = x3 + (size_t)r * K3P + k;
    *(uint32_t*)o3              = h2;
    *(uint32_t*)(o3 + HID)      = h2;
    *(uint32_t*)(o3 + 2 * HID)  = l2;
}

__global__ void conv_w(WPtr wp, __half* __restrict__ w3, __half* __restrict__ w2)
{
    const int w = blockIdx.z;
    const int r = blockIdx.y;
    const int k = (blockIdx.x * blockDim.x + threadIdx.x) * 2;
    float2 x = *(const float2*)(wp.w[w] + (size_t)r * HID + k);
    uint32_t h2, l2; splitH2(x.x, x.y, h2, l2);
    if (w < 3) {
        __half* o = w3 + ((size_t)w * HID + r) * K3P + k;
        *(uint32_t*)o             = h2;
        *(uint32_t*)(o + HID)     = l2;
        *(uint32_t*)(o + 2 * HID) = h2;
    } else {
        __half* o = w2 + ((size_t)(w - 3) * HID + r) * K2P + k;
        *(uint32_t*)o         = h2;
        *(uint32_t*)(o + HID) = l2;
    }
}

__global__ void convT2(const float* __restrict__ in, __half* __restrict__ out)
{
    __shared__ float t[32][33];
    const int r0 = blockIdx.y * 32, c0 = blockIdx.x * 32;
    const int tx = threadIdx.x, ty = threadIdx.y;
#pragma unroll
    for (int i = ty; i < 32; i += 8)
        t[i][tx] = in[(size_t)(r0 + i) * HID + c0 + tx];
    __syncthreads();
#pragma unroll
    for (int i = ty; i < 32; i += 8) {
        float x = t[tx][i];
        const int s = (r0 + tx) & 511;
        const int head = ((r0 >> 9) << 2) + ((c0 + i) >> 9);
        const int dd = (c0 + i) & 511;
        __half h = __float2half_rn(x);
        __half l = __float2half_rn(x - __half2float(h));
        __half* o = out + ((size_t)(head * 512 + dd)) * K2A + s;
        o[0] = h; o[512] = l;
    }
}

// softmax: write P once (512-wide single-h)
__global__ __launch_bounds__(128) void softmax_h(const float* __restrict__ S,
                                                 __half* __restrict__ P)
{
    const size_t row = blockIdx.x;
    const int t = threadIdx.x;
    float4 v = ((const float4*)(S + row * SQ))[t];
    float m = fmaxf(fmaxf(v.x, v.y), fmaxf(v.z, v.w));
#pragma unroll
    for (int o = 16; o; o >>= 1) m = fmaxf(m, __shfl_xor_sync(0xffffffffu, m, o));
    __shared__ float rm[4];
    if ((t & 31) == 0) rm[t >> 5] = m;
    __syncthreads();
    m = fmaxf(fmaxf(rm[0], rm[1]), fmaxf(rm[2], rm[3]));
    v.x = expf(v.x - m); v.y = expf(v.y - m); v.z = expf(v.z - m); v.w = expf(v.w - m);
    float s = v.x + v.y + v.z + v.w;
#pragma unroll
    for (int o = 16; o; o >>= 1) s += __shfl_xor_sync(0xffffffffu, s, o);
    __shared__ float rs[4];
    if ((t & 31) == 0) rs[t >> 5] = s;
    __syncthreads();
    s = rs[0] + rs[1] + rs[2] + rs[3];
    const float inv = 1.0f / s;
    __half2 h0, h1;
    h0.x = __float2half_rn(v.x * inv); h0.y = __float2half_rn(v.y * inv);
    h1.x = __float2half_rn(v.z * inv); h1.y = __float2half_rn(v.w * inv);
    __half* o = P + row * 512 + t * 4;
    *(__half2*)o = h0; *(__half2*)(o + 2) = h1;
}

// ------------------------- host -------------------------
extern "C" void kernel_launch(void* const* d_in, const int* in_sizes, int n_in,
                              void* d_out, int out_size)
{
    const float* X = (const float*)d_in[0];
    WPtr wp = {{(const float*)d_in[1], (const float*)d_in[3], (const float*)d_in[7],
                (const float*)d_in[5], (const float*)d_in[9]}};
    const float* bq  = (const float*)d_in[2];
    const float* bk  = (const float*)d_in[4];
    const float* bv  = (const float*)d_in[6];
    const float* bck = (const float*)d_in[8];
    const float* bcv = (const float*)d_in[10];

    void *x3, *w3, *w2, *ypv, *ypcv, *q3, *k3, *ck3, *vT2, *cvT2, *s1hl, *s2, *ph, *ch;
    cudaGetSymbolAddress(&x3, g_x3);
    cudaGetSymbolAddress(&w3, g_w3);     cudaGetSymbolAddress(&w2, g_w2);
    cudaGetSymbolAddress(&ypv, g_ypv);   cudaGetSymbolAddress(&ypcv, g_ypcv);
    cudaGetSymbolAddress(&q3, g_q3);     cudaGetSymbolAddress(&k3, g_k3);
    cudaGetSymbolAddress(&ck3, g_ck3);   cudaGetSymbolAddress(&vT2, g_vT2);
    cudaGetSymbolAddress(&cvT2, g_cvT2); cudaGetSymbolAddress(&s1hl, g_s1hl);
    cudaGetSymbolAddress(&s2, g_s2);     cudaGetSymbolAddress(&ph, g_ph);
    cudaGetSymbolAddress(&ch, g_ch);

    Ptrs pp3;
    pp3.bias[0] = bq;  pp3.out5[0] = q3;
    pp3.bias[1] = bk;  pp3.out5[1] = k3;
    pp3.bias[2] = bck; pp3.out5[2] = ck3;
    Ptrs pp2;
    pp2.bias[0] = bv;  pp2.out5[0] = ypv;
    pp2.bias[1] = bcv; pp2.out5[1] = ypcv;
    pp2.bias[2] = bv;  pp2.out5[2] = ypv;
    Ptrs pz = pp3;

    static bool init_done = false;
    static cudaStream_t sB;
    static cudaEvent_t evRoot, evB, evProj, evEnd;
    if (!init_done) {
        cudaFuncSetAttribute(gemm_mma<0,0>, cudaFuncAttributeMaxDynamicSharedMemorySize, SMEM_REQ);
        cudaFuncSetAttribute(gemm_mma<0,2>, cudaFuncAttributeMaxDynamicSharedMemorySize, SMEM_REQ);
        cudaFuncSetAttribute(gemm_mma<0,3>, cudaFuncAttributeMaxDynamicSharedMemorySize, SMEM_REQ);
        cudaFuncSetAttribute(gemm_mma<1,0>, cudaFuncAttributeMaxDynamicSharedMemorySize, SMEM_REQ);
        cudaFuncSetAttribute(gemm_mma<2,0>, cudaFuncAttributeMaxDynamicSharedMemorySize, SMEM_REQ);
        cudaFuncSetAttribute(gemm_mma<3,0>, cudaFuncAttributeMaxDynamicSharedMemorySize, SMEM_REQ);
        cudaFuncSetAttribute(gemm_mma<4,2>, cudaFuncAttributeMaxDynamicSharedMemorySize, SMEM_REQ);
        cudaStreamCreateWithFlags(&sB, cudaStreamNonBlocking);
        cudaEventCreateWithFlags(&evRoot, cudaEventDisableTiming);
        cudaEventCreateWithFlags(&evB, cudaEventDisableTiming);
        cudaEventCreateWithFlags(&evProj, cudaEventDisableTiming);
        cudaEventCreateWithFlags(&evEnd, cudaEventDisableTiming);
        init_done = true;
    }

    const long long s3  = (long long)SQ * K3A;
    const long long s2a = (long long)SQ * K2A;
    const long long s1a = (long long)SQ * 512;
    const size_t zo3 = (size_t)32 * SQ * K3A;
    const size_t zo2 = (size_t)32 * SQ * K2A;
    const size_t zo1 = (size_t)32 * SQ * 512;
    const size_t zoS = (size_t)32 * SQ * SQ;
    const size_t zoO = (size_t)8 * SQ * HID;
    dim3 gh(SQ / 128, SQ / 128, 32);

    // roots (default stream) — R13 layout
    conv_x<<<dim3(8, MR), 128>>>(X, (__half*)x3);
    conv_w<<<dim3(8, HID, 5), 128>>>(wp, (__half*)w3, (__half*)w2);
    cudaEventRecord(evRoot, 0);

    // branch B: proj2 (v,cv) + transposes
    cudaStreamWaitEvent(sB, evRoot, 0);
    gemm_mma<3,0><<<dim3(HID / 128, MR / 128, 2), 256, SMEM_REQ, sB>>>(
        (const __half*)x3, 0LL, K3P, (const __half*)w2, (long long)HID * K2P, K2P,
        nullptr, 1.0f, K2P, 0, 0, 0, 0, pp2);
    convT2<<<dim3(HID / 32, MR / 32), dim3(32, 8), 0, sB>>>((const float*)ypv, (__half*)vT2);
    convT2<<<dim3(HID / 32, MR / 32), dim3(32, 8), 0, sB>>>((const float*)ypcv, (__half*)cvT2);
    cudaEventRecord(evB, sB);

    // proj3 (default stream)
    gemm_mma<2,0><<<dim3(HID / 128, MR / 128, 3), 256, SMEM_REQ>>>(
        (const __half*)x3, 0LL, K3P, (const __half*)w3, (long long)HID * K3P, K3P,
        nullptr, 1.0f, K3P, 0, 0, 0, 0, pp3);
    cudaEventRecord(evProj, 0);

    // ----- group 1 (heads 32..63) on sB -----
    cudaStreamWaitEvent(sB, evProj, 0);
    gemm_mma<1,0><<<gh, 256, SMEM_REQ, sB>>>(
        (const __half*)q3 + zo3, s3, K3A, (const __half*)k3 + zo3, s3, K3A,
        (__half*)s1hl + zo2, 1.0f, K3A, 0, 0, 0, 0, pz);
    gemm_mma<0,3><<<gh, 256, SMEM_REQ, sB>>>(
        (const __half*)s1hl + zo2, s2a, K2A, (const __half*)ck3 + zo3, s3, K3A,
        (float*)s2 + zoS, SCALE_F, K3A, (long long)SQ * SQ, 0, 0, SQ, pz);
    softmax_h<<<32 * SQ, 128, 0, sB>>>((const float*)s2 + zoS, (__half*)ph + zo1);
    gemm_mma<4,2><<<gh, 256, SMEM_REQ, sB>>>(
        (const __half*)ph + zo1, s1a, 512, (const __half*)vT2 + zo2, s2a, K2A,
        (__half*)ch + zo1, 1.0f, K2A, 0, 0, 0, 0, pz);
    gemm_mma<0,2><<<gh, 256, SMEM_REQ, sB>>>(
        (const __half*)ch + zo1, s1a, 512, (const __half*)cvT2 + zo2, s2a, K2A,
        (float*)d_out + zoO, 1.0f, K2A, 0, (long long)SQ * HID, 512, HID, pz);
    cudaEventRecord(evEnd, sB);

    // ----- group 0 (heads 0..31) on default stream -----
    gemm_mma<1,0><<<gh, 256, SMEM_REQ>>>(
        (const __half*)q3, s3, K3A, (const __half*)k3, s3, K3A,
        s1hl, 1.0f, K3A, 0, 0, 0, 0, pz);
    gemm_mma<0,3><<<gh, 256, SMEM_REQ>>>(
        (const __half*)s1hl, s2a, K2A, (const __half*)ck3, s3, K3A,
        s2, SCALE_F, K3A, (long long)SQ * SQ, 0, 0, SQ, pz);
    softmax_h<<<32 * SQ, 128>>>((const float*)s2, (__half*)ph);
    cudaStreamWaitEvent(0, evB, 0);
    gemm_mma<4,2><<<gh, 256, SMEM_REQ>>>(
        (const __half*)ph, s1a, 512, (const __half*)vT2, s2a, K2A,
        ch, 1.0f, K2A, 0, 0, 0, 0, pz);
    gemm_mma<0,2><<<gh, 256, SMEM_REQ>>>(
        (const __half*)ch, s1a, 512, (const __half*)cvT2, s2a, K2A,
        d_out, 1.0f, K2A, 0, (long long)SQ * HID, 512, HID, pz);

    // join sB back into the harness's stream
    cudaStreamWaitEvent(0, evEnd, 0);
}

// round 17
// speedup vs baseline: 1.0193x; 1.0078x over previous
#include <cuda_runtime.h>
#include <cuda_fp16.h>
#include <cstdint>
#include <cstddef>
#include <math.h>

#define SQ  512
#define HID 2048
#define NZ  64
#define MR  8192
#define K3A 1536
#define K2A 1024
#define K3P 6144
#define K2P 4096

static const float SCALE_F = 0.04419417382415922f;

// ------------------------- scratch -------------------------
__device__ __align__(1024) __half g_x3  [(size_t)MR*K3P];   // [h|h|l]
__device__ __align__(1024) __half g_w3  [(size_t)3*HID*K3P];
__device__ __align__(1024) __half g_w2  [(size_t)2*HID*K2P];
__device__ __align__(1024) float  g_ypv [(size_t)MR*HID];
__device__ __align__(1024) float  g_ypcv[(size_t)MR*HID];
__device__ __align__(1024) __half g_q2  [(size_t)NZ*SQ*K2A];  // [h|l]
__device__ __align__(1024) __half g_k2  [(size_t)NZ*SQ*K2A];  // [h|l]
__device__ __align__(1024) __half g_ck2 [(size_t)NZ*SQ*K2A];  // [h|l]
__device__ __align__(1024) __half g_vT2 [(size_t)NZ*SQ*K2A];
__device__ __align__(1024) __half g_cvT2[(size_t)NZ*SQ*K2A];
__device__ __align__(1024) __half g_s1hl[(size_t)NZ*SQ*K2A];  // s1 [h|l]
__device__ __align__(1024) float  g_s2  [(size_t)NZ*SQ*SQ];
__device__ __align__(1024) __half g_ph  [(size_t)NZ*SQ*SQ];   // P single-h
__device__ __align__(1024) __half g_ch  [(size_t)NZ*SQ*SQ];   // ctx single-h

// ------------------------- helpers -------------------------
#define CP16(dst, src) asm volatile("cp.async.cg.shared.global [%0], [%1], 16;" \
    :: "r"(dst), "l"(src))
#define CP_COMMIT() asm volatile("cp.async.commit_group;")
#define CP_WAIT(n)  asm volatile("cp.async.wait_group %0;" :: "n"(n))

__device__ __forceinline__ void ldsm4(uint32_t* d, uint32_t addr) {
    asm volatile("ldmatrix.sync.aligned.m8n8.x4.shared.b16 {%0,%1,%2,%3}, [%4];"
        : "=r"(d[0]), "=r"(d[1]), "=r"(d[2]), "=r"(d[3]) : "r"(addr));
}
__device__ __forceinline__ void mma16816(float* c, const uint32_t* a, uint32_t b0, uint32_t b1) {
    asm volatile("mma.sync.aligned.m16n8k16.row.col.f32.f16.f16.f32 "
        "{%0,%1,%2,%3}, {%4,%5,%6,%7}, {%8,%9}, {%0,%1,%2,%3};"
        : "+f"(c[0]), "+f"(c[1]), "+f"(c[2]), "+f"(c[3])
        : "r"(a[0]), "r"(a[1]), "r"(a[2]), "r"(a[3]), "r"(b0), "r"(b1));
}
__device__ __forceinline__ void splitH2(float x, float y, uint32_t& h2, uint32_t& l2) {
    __half2 h, l;
    h.x = __float2half_rn(x); l.x = __float2half_rn(x - __half2float(h.x));
    h.y = __float2half_rn(y); l.y = __float2half_rn(y - __half2float(h.y));
    h2 = *reinterpret_cast<uint32_t*>(&h);
    l2 = *reinterpret_cast<uint32_t*>(&l);
}

struct Ptrs { const float* bias[3]; void* out5[3]; };
struct WPtr { const float* w[5]; };

#define STGB 10240u
#define NSTG 5
#define SMEM_REQ (2u * NSTG * STGB)

// ------------------------- GEMM (mma.sync f16->f32, NT) ---------------------
// EPI 0: fp32 out; EPI 1: s1 [h|l]; EPI 2: proj3 head-remap [h|l];
// EPI 3: proj2 fp32+bias; EPI 4: single-h out (512-wide)
// AMAP: 0 = kt; 2 = kt&15 (512-wide single-h); 3 = kt<16?kt:kt-16 (1024 [h|l] -> h,h,l)
// BMAP: 0 = kt; 1 = kt&31 (1024 [h|l] -> h,l,h)
template <int EPI, int AMAP, int BMAP>
__global__ __launch_bounds__(256, 2) void gemm_mma(
    const __half* __restrict__ A, long long sAz, int lda,
    const __half* __restrict__ B, long long sBz, int ldb,
    void* outp, float alpha, int K,
    long long sZ, long long sCb, long long sCh, int ldc, Ptrs pp)
{
    extern __shared__ char smraw[];
    const uint32_t baseA = (uint32_t)__cvta_generic_to_shared(smraw);
    const uint32_t baseB = baseA + NSTG * STGB;

    const int tid = threadIdx.x;
    const int lane = tid & 31, wid = tid >> 5;
    const int wm = wid >> 2, wn = wid & 3;
    const int m0 = blockIdx.y * 128, n0 = blockIdx.x * 128, z = blockIdx.z;

    const __half* Az = A + (size_t)z * sAz;
    const __half* Bz = B + (size_t)z * sBz;

    const int lr = tid >> 2, lq = tid & 3;
    const __half* gA0 = Az + (size_t)(m0 + lr) * lda + lq * 8;
    const __half* gA1 = Az + (size_t)(m0 + lr + 64) * lda + lq * 8;
    const __half* gB0 = Bz + (size_t)(n0 + lr) * ldb + lq * 8;
    const __half* gB1 = Bz + (size_t)(n0 + lr + 64) * ldb + lq * 8;

    const uint32_t dA0 = baseA + lr * 80 + lq * 16;
    const uint32_t dA1 = baseA + (lr + 64) * 80 + lq * 16;
    const uint32_t dB0 = baseB + lr * 80 + lq * 16;
    const uint32_t dB1 = baseB + (lr + 64) * 80 + lq * 16;

    const int lrow = (lane & 7) + ((lane >> 3) & 1) * 8;
    const int lchunk = lane >> 4;
    const uint32_t aAddr = (wm * 64 + lrow) * 80 + lchunk * 16;
    const uint32_t bAddr = (wn * 32 + lrow) * 80 + lchunk * 16;

    float acc[4][4][4];
#pragma unroll
    for (int i = 0; i < 4; i++)
#pragma unroll
        for (int j = 0; j < 4; j++) { acc[i][j][0]=0.f; acc[i][j][1]=0.f; acc[i][j][2]=0.f; acc[i][j][3]=0.f; }

#define AOFF(kt) ((size_t)((AMAP == 0) ? (kt) : (AMAP == 2) ? ((kt) & 15) : (((kt) < 16) ? (kt) : (kt) - 16)) * 32)
#define BOFF(kt) ((size_t)((BMAP == 0) ? (kt) : ((kt) & 31)) * 32)

#define LOADTILE(kt, st) do { \
    const size_t ka = AOFF(kt); \
    const size_t kb_ = BOFF(kt); \
    const uint32_t so = (uint32_t)(st) * STGB; \
    CP16(dA0 + so, gA0 + ka); CP16(dA1 + so, gA1 + ka); \
    CP16(dB0 + so, gB0 + kb_); CP16(dB1 + so, gB1 + kb_); \
} while (0)

#define COMPUTE_CHUNK(st) do { \
    const uint32_t so = (uint32_t)(st) * STGB; \
    _Pragma("unroll") \
    for (int k16 = 0; k16 < 2; ++k16) { \
        const uint32_t kb = so + k16 * 32; \
        uint32_t a[4][4], bq[2][4]; \
        _Pragma("unroll") \
        for (int mi = 0; mi < 4; ++mi) ldsm4(a[mi], baseA + kb + aAddr + mi * (16*80)); \
        _Pragma("unroll") \
        for (int j = 0; j < 2; ++j) ldsm4(bq[j], baseB + kb + bAddr + j * (16*80)); \
        _Pragma("unroll") \
        for (int mi = 0; mi < 4; ++mi) \
            _Pragma("unroll") \
            for (int ni = 0; ni < 4; ++ni) \
                mma16816(acc[mi][ni], a[mi], bq[ni >> 1][ni & 1], bq[ni >> 1][2 + (ni & 1)]); \
    } \
} while (0)

    const int KT = K / 32;
    LOADTILE(0, 0); CP_COMMIT();
    LOADTILE(1, 1); CP_COMMIT();
    LOADTILE(2, 2); CP_COMMIT();

    int cs = 0, ls = 3;
    for (int kt = 0; kt < KT; kt += 2) {
        CP_WAIT(1);
        __syncthreads();
        const int ls2 = (ls + 1 == NSTG) ? 0 : ls + 1;
        if (kt + 3 < KT) { LOADTILE(kt + 3, ls); CP_COMMIT(); } else CP_COMMIT();
        if (kt + 4 < KT) { LOADTILE(kt + 4, ls2); CP_COMMIT(); } else CP_COMMIT();
        const int cs2 = (cs + 1 == NSTG) ? 0 : cs + 1;
        COMPUTE_CHUNK(cs);
        COMPUTE_CHUNK(cs2);
        cs = (cs2 + 1 == NSTG) ? 0 : cs2 + 1;
        ls = (ls2 + 1 == NSTG) ? 0 : ls2 + 1;
    }
#undef LOADTILE
#undef COMPUTE_CHUNK
#undef AOFF
#undef BOFF

    float* obase = nullptr;
    __half* cbase = nullptr;
    if (EPI == 0) obase = (float*)outp + (size_t)z * sZ + (size_t)(z >> 2) * sCb + (size_t)(z & 3) * sCh;
    if (EPI == 1) cbase = (__half*)outp + (size_t)z * SQ * K2A;
    if (EPI == 4) cbase = (__half*)outp + (size_t)z * SQ * 512;

#pragma unroll
    for (int mi = 0; mi < 4; ++mi)
#pragma unroll
        for (int ni = 0; ni < 4; ++ni) {
            const int r0 = m0 + wm * 64 + mi * 16 + (lane >> 2);
            const int c  = n0 + wn * 32 + ni * 8 + (lane & 3) * 2;
#pragma unroll
            for (int hh = 0; hh < 2; ++hh) {
                const int r = r0 + hh * 8;
                float v0 = acc[mi][ni][hh * 2], v1 = acc[mi][ni][hh * 2 + 1];
                if (EPI == 0) {
                    float2 f; f.x = v0 * alpha; f.y = v1 * alpha;
                    *(float2*)(obase + (size_t)r * ldc + c) = f;
                } else if (EPI == 1) {
                    uint32_t h2, l2; splitH2(v0, v1, h2, l2);
                    __half* o = cbase + (size_t)r * K2A + c;
                    *(uint32_t*)o = h2; *(uint32_t*)(o + 512) = l2;
                } else if (EPI == 4) {
                    uint32_t h2, l2; splitH2(v0, v1, h2, l2);
                    __half* o = cbase + (size_t)r * 512 + c;
                    *(uint32_t*)o = h2;
                } else if (EPI == 3) {
                    v0 += pp.bias[z][c]; v1 += pp.bias[z][c + 1];
                    float2 f; f.x = v0; f.y = v1;
                    *(float2*)((float*)pp.out5[z] + (size_t)r * HID + c) = f;
                } else {   // EPI == 2: proj3 -> head-remapped [h|l]
                    v0 += pp.bias[z][c]; v1 += pp.bias[z][c + 1];
                    uint32_t h2, l2; splitH2(v0, v1, h2, l2);
                    const int head = ((r >> 9) << 2) + (c >> 9);
                    __half* o = (__half*)pp.out5[z]
                        + ((size_t)(head * 512 + (r & 511))) * K2A + (c & 511);
                    *(uint32_t*)o = h2;
                    *(uint32_t*)(o + 512) = l2;
                }
            }
        }
}

// ------------------------- conversions -------------------------
__global__ void conv_x(const float* __restrict__ in, __half* __restrict__ x3)
{
    const int r = blockIdx.y;
    const int k = (blockIdx.x * blockDim.x + threadIdx.x) * 2;
    float2 x = *(const float2*)(in + (size_t)r * HID + k);
    uint32_t h2, l2; splitH2(x.x, x.y, h2, l2);
    __half* o3 = x3 + (size_t)r * K3P + k;
    *(uint32_t*)o3              = h2;
    *(uint32_t*)(o3 + HID)      = h2;
    *(uint32_t*)(o3 + 2 * HID)  = l2;
}

__global__ void conv_w(WPtr wp, __half* __restrict__ w3, __half* __restrict__ w2)
{
    const int w = blockIdx.z;
    const int r = blockIdx.y;
    const int k = (blockIdx.x * blockDim.x + threadIdx.x) * 2;
    float2 x = *(const float2*)(wp.w[w] + (size_t)r * HID + k);
    uint32_t h2, l2; splitH2(x.x, x.y, h2, l2);
    if (w < 3) {
        __half* o = w3 + ((size_t)w * HID + r) * K3P + k;
        *(uint32_t*)o             = h2;
        *(uint32_t*)(o + HID)     = l2;
        *(uint32_t*)(o + 2 * HID) = h2;
    } else {
        __half* o = w2 + ((size_t)(w - 3) * HID + r) * K2P + k;
        *(uint32_t*)o         = h2;
        *(uint32_t*)(o + HID) = l2;
    }
}

__global__ void convT2(const float* __restrict__ in, __half* __restrict__ out)
{
    __shared__ float t[32][33];
    const int r0 = blockIdx.y * 32, c0 = blockIdx.x * 32;
    const int tx = threadIdx.x, ty = threadIdx.y;
#pragma unroll
    for (int i = ty; i < 32; i += 8)
        t[i][tx] = in[(size_t)(r0 + i) * HID + c0 + tx];
    __syncthreads();
#pragma unroll
    for (int i = ty; i < 32; i += 8) {
        float x = t[tx][i];
        const int s = (r0 + tx) & 511;
        const int head = ((r0 >> 9) << 2) + ((c0 + i) >> 9);
        const int dd = (c0 + i) & 511;
        __half h = __float2half_rn(x);
        __half l = __float2half_rn(x - __half2float(h));
        __half* o = out + ((size_t)(head * 512 + dd)) * K2A + s;
        o[0] = h; o[512] = l;
    }
}

__global__ __launch_bounds__(128) void softmax_h(const float* __restrict__ S,
                                                 __half* __restrict__ P)
{
    const size_t row = blockIdx.x;
    const int t = threadIdx.x;
    float4 v = ((const float4*)(S + row * SQ))[t];
    float m = fmaxf(fmaxf(v.x, v.y), fmaxf(v.z, v.w));
#pragma unroll
    for (int o = 16; o; o >>= 1) m = fmaxf(m, __shfl_xor_sync(0xffffffffu, m, o));
    __shared__ float rm[4];
    if ((t & 31) == 0) rm[t >> 5] = m;
    __syncthreads();
    m = fmaxf(fmaxf(rm[0], rm[1]), fmaxf(rm[2], rm[3]));
    v.x = expf(v.x - m); v.y = expf(v.y - m); v.z = expf(v.z - m); v.w = expf(v.w - m);
    float s = v.x + v.y + v.z + v.w;
#pragma unroll
    for (int o = 16; o; o >>= 1) s += __shfl_xor_sync(0xffffffffu, s, o);
    __shared__ float rs[4];
    if ((t & 31) == 0) rs[t >> 5] = s;
    __syncthreads();
    s = rs[0] + rs[1] + rs[2] + rs[3];
    const float inv = 1.0f / s;
    __half2 h0, h1;
    h0.x = __float2half_rn(v.x * inv); h0.y = __float2half_rn(v.y * inv);
    h1.x = __float2half_rn(v.z * inv); h1.y = __float2half_rn(v.w * inv);
    __half* o = P + row * 512 + t * 4;
    *(__half2*)o = h0; *(__half2*)(o + 2) = h1;
}

// ------------------------- host -------------------------
extern "C" void kernel_launch(void* const* d_in, const int* in_sizes, int n_in,
                              void* d_out, int out_size)
{
    const float* X = (const float*)d_in[0];
    WPtr wp = {{(const float*)d_in[1], (const float*)d_in[3], (const float*)d_in[7],
                (const float*)d_in[5], (const float*)d_in[9]}};
    const float* bq  = (const float*)d_in[2];
    const float* bk  = (const float*)d_in[4];
    const float* bv  = (const float*)d_in[6];
    const float* bck = (const float*)d_in[8];
    const float* bcv = (const float*)d_in[10];

    void *x3, *w3, *w2, *ypv, *ypcv, *q2, *k2, *ck2, *vT2, *cvT2, *s1hl, *s2, *ph, *ch;
    cudaGetSymbolAddress(&x3, g_x3);
    cudaGetSymbolAddress(&w3, g_w3);     cudaGetSymbolAddress(&w2, g_w2);
    cudaGetSymbolAddress(&ypv, g_ypv);   cudaGetSymbolAddress(&ypcv, g_ypcv);
    cudaGetSymbolAddress(&q2, g_q2);     cudaGetSymbolAddress(&k2, g_k2);
    cudaGetSymbolAddress(&ck2, g_ck2);   cudaGetSymbolAddress(&vT2, g_vT2);
    cudaGetSymbolAddress(&cvT2, g_cvT2); cudaGetSymbolAddress(&s1hl, g_s1hl);
    cudaGetSymbolAddress(&s2, g_s2);     cudaGetSymbolAddress(&ph, g_ph);
    cudaGetSymbolAddress(&ch, g_ch);

    Ptrs pp3;
    pp3.bias[0] = bq;  pp3.out5[0] = q2;
    pp3.bias[1] = bk;  pp3.out5[1] = k2;
    pp3.bias[2] = bck; pp3.out5[2] = ck2;
    Ptrs pp2;
    pp2.bias[0] = bv;  pp2.out5[0] = ypv;
    pp2.bias[1] = bcv; pp2.out5[1] = ypcv;
    pp2.bias[2] = bv;  pp2.out5[2] = ypv;
    Ptrs pz = pp3;

    static bool init_done = false;
    static cudaStream_t sB;
    static cudaEvent_t evRoot, evB, evProj, evEnd;
    if (!init_done) {
        cudaFuncSetAttribute(gemm_mma<0,2,0>, cudaFuncAttributeMaxDynamicSharedMemorySize, SMEM_REQ);
        cudaFuncSetAttribute(gemm_mma<0,3,1>, cudaFuncAttributeMaxDynamicSharedMemorySize, SMEM_REQ);
        cudaFuncSetAttribute(gemm_mma<1,3,1>, cudaFuncAttributeMaxDynamicSharedMemorySize, SMEM_REQ);
        cudaFuncSetAttribute(gemm_mma<2,0,0>, cudaFuncAttributeMaxDynamicSharedMemorySize, SMEM_REQ);
        cudaFuncSetAttribute(gemm_mma<3,0,0>, cudaFuncAttributeMaxDynamicSharedMemorySize, SMEM_REQ);
        cudaFuncSetAttribute(gemm_mma<4,2,0>, cudaFuncAttributeMaxDynamicSharedMemorySize, SMEM_REQ);
        cudaStreamCreateWithFlags(&sB, cudaStreamNonBlocking);
        cudaEventCreateWithFlags(&evRoot, cudaEventDisableTiming);
        cudaEventCreateWithFlags(&evB, cudaEventDisableTiming);
        cudaEventCreateWithFlags(&evProj, cudaEventDisableTiming);
        cudaEventCreateWithFlags(&evEnd, cudaEventDisableTiming);
        init_done = true;
    }

    const long long s2a = (long long)SQ * K2A;
    const long long s1a = (long long)SQ * 512;
    const size_t zo2 = (size_t)32 * SQ * K2A;
    const size_t zo1 = (size_t)32 * SQ * 512;
    const size_t zoS = (size_t)32 * SQ * SQ;
    const size_t zoO = (size_t)8 * SQ * HID;
    dim3 gh(SQ / 128, SQ / 128, 32);

    // roots (default stream)
    conv_x<<<dim3(8, MR), 128>>>(X, (__half*)x3);
    conv_w<<<dim3(8, HID, 5), 128>>>(wp, (__half*)w3, (__half*)w2);
    cudaEventRecord(evRoot, 0);

    // branch B: proj2 (v,cv) + transposes
    cudaStreamWaitEvent(sB, evRoot, 0);
    gemm_mma<3,0,0><<<dim3(HID / 128, MR / 128, 2), 256, SMEM_REQ, sB>>>(
        (const __half*)x3, 0LL, K3P, (const __half*)w2, (long long)HID * K2P, K2P,
        nullptr, 1.0f, K2P, 0, 0, 0, 0, pp2);
    convT2<<<dim3(HID / 32, MR / 32), dim3(32, 8), 0, sB>>>((const float*)ypv, (__half*)vT2);
    convT2<<<dim3(HID / 32, MR / 32), dim3(32, 8), 0, sB>>>((const float*)ypcv, (__half*)cvT2);
    cudaEventRecord(evB, sB);

    // proj3 (default stream) -> dedup [h|l] outputs
    gemm_mma<2,0,0><<<dim3(HID / 128, MR / 128, 3), 256, SMEM_REQ>>>(
        (const __half*)x3, 0LL, K3P, (const __half*)w3, (long long)HID * K3P, K3P,
        nullptr, 1.0f, K3P, 0, 0, 0, 0, pp3);
    cudaEventRecord(evProj, 0);

    // ----- group 1 (heads 32..63) on sB -----
    cudaStreamWaitEvent(sB, evProj, 0);
    gemm_mma<1,3,1><<<gh, 256, SMEM_REQ, sB>>>(
        (const __half*)q2 + zo2, s2a, K2A, (const __half*)k2 + zo2, s2a, K2A,
        (__half*)s1hl + zo2, 1.0f, K3A, 0, 0, 0, 0, pz);
    gemm_mma<0,3,1><<<gh, 256, SMEM_REQ, sB>>>(
        (const __half*)s1hl + zo2, s2a, K2A, (const __half*)ck2 + zo2, s2a, K2A,
        (float*)s2 + zoS, SCALE_F, K3A, (long long)SQ * SQ, 0, 0, SQ, pz);
    softmax_h<<<32 * SQ, 128, 0, sB>>>((const float*)s2 + zoS, (__half*)ph + zo1);
    gemm_mma<4,2,0><<<gh, 256, SMEM_REQ, sB>>>(
        (const __half*)ph + zo1, s1a, 512, (const __half*)vT2 + zo2, s2a, K2A,
        (__half*)ch + zo1, 1.0f, K2A, 0, 0, 0, 0, pz);
    gemm_mma<0,2,0><<<gh, 256, SMEM_REQ, sB>>>(
        (const __half*)ch + zo1, s1a, 512, (const __half*)cvT2 + zo2, s2a, K2A,
        (float*)d_out + zoO, 1.0f, K2A, 0, (long long)SQ * HID, 512, HID, pz);
    cudaEventRecord(evEnd, sB);

    // ----- group 0 (heads 0..31) on default stream -----
    gemm_mma<1,3,1><<<gh, 256, SMEM_REQ>>>(
        (const __half*)q2, s2a, K2A, (const __half*)k2, s2a, K2A,
        s1hl, 1.0f, K3A, 0, 0, 0, 0, pz);
    gemm_mma<0,3,1><<<gh, 256, SMEM_REQ>>>(
        (const __half*)s1hl, s2a, K2A, (const __half*)ck2, s2a, K2A,
        s2, SCALE_F, K3A, (long long)SQ * SQ, 0, 0, SQ, pz);
    softmax_h<<<32 * SQ, 128>>>((const float*)s2, (__half*)ph);
    cudaStreamWaitEvent(0, evB, 0);
    gemm_mma<4,2,0><<<gh, 256, SMEM_REQ>>>(
        (const __half*)ph, s1a, 512, (const __half*)vT2, s2a, K2A,
        ch, 1.0f, K2A, 0, 0, 0, 0, pz);
    gemm_mma<0,2,0><<<gh, 256, SMEM_REQ>>>(
        (const __half*)ch, s1a, 512, (const __half*)cvT2, s2a, K2A,
        d_out, 1.0f, K2A, 0, (long long)SQ * HID, 512, HID, pz);

    // join sB back into the harness's stream
    cudaStreamWaitEvent(0, evEnd, 0);
}